// round 9
// baseline (speedup 1.0000x reference)
#include <cuda_runtime.h>
#include <cuda_fp16.h>
#include <cstdint>

// out[src] += edge_attr[e] * x[dst]   (E=1.6M, N=100k, D=32)
// Inputs: edge_index int32 [2,E], edge_attr f32 [E], x f32 [N,32]
// Output: f32 [N,32]
//
// R9: the fp32 feature atomics (1.6M x 128B RMW) are the wall (~40us of L2
// RMW-sector throughput). Build a CSR grouping by src each launch (counters +
// scan + scatter, int-atomics only), then a warp-per-node gather pass that
// accumulates in registers and does ONE plain store per node. fp16 x copy
// halves gather read sectors.

#define N_CAP   131072
#define E_CAP   1700000
#define CHUNK   1024
#define NB_CAP  (N_CAP / CHUNK)          // 128

__device__ int     g_count[N_CAP];       // counts, then reused as cursor
__device__ int     g_rowptr[N_CAP + 1];
__device__ int     g_partials[NB_CAP];
__device__ uint2   g_csr[E_CAP];         // (dst, attr bits)
__device__ __half2 g_xh[N_CAP * 16];     // fp16 copy of x

__device__ __forceinline__ unsigned short ldcg_h(const __half* p) {
    unsigned short v;
    asm volatile("ld.global.cg.u16 %0, [%1];" : "=h"(v) : "l"(p));
    return v;
}
__device__ __forceinline__ void red_add_v4(float* addr, float4 v) {
    asm volatile("red.global.add.v4.f32 [%0], {%1, %2, %3, %4};"
                 :: "l"(addr), "f"(v.x), "f"(v.y), "f"(v.z), "f"(v.w)
                 : "memory");
}
__device__ __forceinline__ float4 ldcg_v4f(const float* p) {
    float4 v;
    asm volatile("ld.global.cg.v4.f32 {%0, %1, %2, %3}, [%4];"
                 : "=f"(v.x), "=f"(v.y), "=f"(v.z), "=f"(v.w)
                 : "l"(p));
    return v;
}

// ---- 1. prep: zero counters (padded) + convert x -> fp16 ------------------
__global__ void prep_kernel(const float* __restrict__ x, int nx4, int n_pad) {
    int i = blockIdx.x * blockDim.x + threadIdx.x;
    int stride = gridDim.x * blockDim.x;
    int nmax = nx4 > n_pad ? nx4 : n_pad;
    for (; i < nmax; i += stride) {
        if (i < n_pad) g_count[i] = 0;
        if (i < nx4) {
            float4 f = ((const float4*)x)[i];
            g_xh[i * 2]     = __floats2half2_rn(f.x, f.y);
            g_xh[i * 2 + 1] = __floats2half2_rn(f.z, f.w);
        }
    }
}

// ---- 2. count edges per src ----------------------------------------------
__global__ void count_kernel(const int* __restrict__ edge_index, int E) {
    int i = blockIdx.x * blockDim.x + threadIdx.x;
    int stride = gridDim.x * blockDim.x;
    for (; i < E; i += stride)
        atomicAdd(&g_count[edge_index[i]], 1);
}

// ---- 3. per-chunk sums ----------------------------------------------------
__global__ void scanA_kernel() {
    int b = blockIdx.x, t = threadIdx.x;          // 256 threads, CHUNK=1024
    int4 c = ((const int4*)g_count)[b * 256 + t];
    int s = c.x + c.y + c.z + c.w;
    #pragma unroll
    for (int d = 16; d > 0; d >>= 1) s += __shfl_down_sync(0xffffffffu, s, d);
    __shared__ int wsum[8];
    if ((t & 31) == 0) wsum[t >> 5] = s;
    __syncthreads();
    if (t == 0) {
        int tot = 0;
        #pragma unroll
        for (int k = 0; k < 8; k++) tot += wsum[k];
        g_partials[b] = tot;
    }
}

// ---- 4. scan the (<=128) partials ----------------------------------------
__global__ void scanB_kernel(int nb, int n_nodes) {
    int t = threadIdx.x, lane = t & 31, w = t >> 5;   // 128 threads
    __shared__ int wsum[4];
    int v = (t < nb) ? g_partials[t] : 0;
    int inc = v;
    #pragma unroll
    for (int d = 1; d < 32; d <<= 1) {
        int u = __shfl_up_sync(0xffffffffu, inc, d);
        if (lane >= d) inc += u;
    }
    if (lane == 31) wsum[w] = inc;
    __syncthreads();
    int woff = 0;
    for (int k = 0; k < w; k++) woff += wsum[k];
    int excl = woff + inc - v;
    if (t < nb) g_partials[t] = excl;
    if (t == nb - 1) g_rowptr[n_nodes] = excl + v;    // total = E
}

// ---- 5. chunk-local exclusive scan -> rowptr + cursor ---------------------
__global__ void scanC_kernel() {
    int b = blockIdx.x, t = threadIdx.x, lane = t & 31, w = t >> 5;
    int4 c = ((const int4*)g_count)[b * 256 + t];
    int p4 = c.x + c.y + c.z + c.w;
    int inc = p4;
    #pragma unroll
    for (int d = 1; d < 32; d <<= 1) {
        int u = __shfl_up_sync(0xffffffffu, inc, d);
        if (lane >= d) inc += u;
    }
    __shared__ int wsum[8];
    if (lane == 31) wsum[w] = inc;
    __syncthreads();
    int woff = 0;
    for (int k = 0; k < w; k++) woff += wsum[k];
    int start = g_partials[b] + woff + inc - p4;       // exclusive start of elem 0

    int idx = (b * 256 + t) * 4;
    int4 rp, cur;
    rp.x = start;            cur.x = rp.x;
    rp.y = rp.x + c.x;       cur.y = rp.y;
    rp.z = rp.y + c.y;       cur.z = rp.z;
    rp.w = rp.z + c.z;       cur.w = rp.w;
    ((int4*)g_rowptr)[idx / 4] = rp;
    ((int4*)g_count)[idx / 4]  = cur;                  // cursor = rowptr copy
}

// ---- 6. scatter edges into CSR order -------------------------------------
__global__ void build_kernel(const int* __restrict__ edge_index,
                             const float* __restrict__ edge_attr, int E) {
    int i = blockIdx.x * blockDim.x + threadIdx.x;
    int stride = gridDim.x * blockDim.x;
    for (; i < E; i += stride) {
        int s = edge_index[i];
        int d = edge_index[E + i];
        float a = edge_attr[i];
        int pos = atomicAdd(&g_count[s], 1);
        g_csr[pos] = make_uint2((unsigned)d, __float_as_uint(a));
    }
}

// ---- 7. gather: warp per node, register accumulation, plain store ---------
__global__ __launch_bounds__(256) void gather_kernel(float* __restrict__ out,
                                                     int n_nodes) {
    int lane = threadIdx.x & 31;
    int n = (blockIdx.x * blockDim.x + threadIdx.x) >> 5;
    if (n >= n_nodes) return;

    int beg = __ldg(&g_rowptr[n]);
    int end = __ldg(&g_rowptr[n + 1]);
    const __half* xh = (const __half*)g_xh;

    float acc = 0.0f;
    int i = beg;
    for (; i + 4 <= end; i += 4) {
        uint2 m0 = __ldg(&g_csr[i]);
        uint2 m1 = __ldg(&g_csr[i + 1]);
        uint2 m2 = __ldg(&g_csr[i + 2]);
        uint2 m3 = __ldg(&g_csr[i + 3]);
        float x0 = __half2float(__ushort_as_half(ldcg_h(xh + (long)m0.x * 32 + lane)));
        float x1 = __half2float(__ushort_as_half(ldcg_h(xh + (long)m1.x * 32 + lane)));
        float x2 = __half2float(__ushort_as_half(ldcg_h(xh + (long)m2.x * 32 + lane)));
        float x3 = __half2float(__ushort_as_half(ldcg_h(xh + (long)m3.x * 32 + lane)));
        acc = fmaf(__uint_as_float(m0.y), x0, acc);
        acc = fmaf(__uint_as_float(m1.y), x1, acc);
        acc = fmaf(__uint_as_float(m2.y), x2, acc);
        acc = fmaf(__uint_as_float(m3.y), x3, acc);
    }
    for (; i < end; i++) {
        uint2 m = __ldg(&g_csr[i]);
        float xv = __half2float(__ushort_as_half(ldcg_h(xh + (long)m.x * 32 + lane)));
        acc = fmaf(__uint_as_float(m.y), xv, acc);
    }
    out[(long)n * 32 + lane] = acc;
}

// ---- fallback (R4-style) for oversize inputs ------------------------------
__global__ void zero_out_kernel(float4* __restrict__ out, int n4) {
    int i = blockIdx.x * blockDim.x + threadIdx.x;
    int stride = gridDim.x * blockDim.x;
    float4 z = make_float4(0.f, 0.f, 0.f, 0.f);
    for (; i < n4; i += stride) out[i] = z;
}
__global__ __launch_bounds__(256) void scatter_f_kernel(
        const int* __restrict__ edge_index,
        const float* __restrict__ edge_attr,
        const float* __restrict__ x,
        float* __restrict__ out, int E) {
    int lane = threadIdx.x & 31;
    int slot = lane >> 3;
    int fofs = (lane & 7) << 2;
    int warp = (blockIdx.x * blockDim.x + threadIdx.x) >> 5;
    int base = warp * 32;
    if (base >= E) return;
    for (int i = 0; i < 8; i++) {
        int e = base + i * 4 + slot;
        if (e < E) {
            int src = __ldg(&edge_index[e]);
            int dst = __ldg(&edge_index[E + e]);
            float a = __ldg(&edge_attr[e]);
            float4 v = ldcg_v4f(x + (long)dst * 32 + fofs);
            v.x *= a; v.y *= a; v.z *= a; v.w *= a;
            red_add_v4(out + (long)src * 32 + fofs, v);
        }
    }
}

extern "C" void kernel_launch(void* const* d_in, const int* in_sizes, int n_in,
                              void* d_out, int out_size) {
    const int*   edge_index = (const int*)d_in[0];
    const float* edge_attr  = (const float*)d_in[1];
    const float* x          = (const float*)d_in[2];
    float*       out        = (float*)d_out;

    int E       = in_sizes[0] / 2;
    int nx      = in_sizes[2];
    int n_nodes = nx / 32;

    if (n_nodes <= N_CAP && E <= E_CAP && (nx & 3) == 0) {
        int nb    = (n_nodes + CHUNK - 1) / CHUNK;
        int n_pad = nb * CHUNK;
        int nx4   = nx / 4;

        int pmax = nx4 > n_pad ? nx4 : n_pad;
        int pb = (pmax + 255) / 256; if (pb > 4096) pb = 4096;
        prep_kernel<<<pb, 256>>>(x, nx4, n_pad);

        int eb = (E + 255) / 256; if (eb > 4096) eb = 4096;
        count_kernel<<<eb, 256>>>(edge_index, E);

        scanA_kernel<<<nb, 256>>>();
        scanB_kernel<<<1, 128>>>(nb, n_nodes);
        scanC_kernel<<<nb, 256>>>();

        build_kernel<<<eb, 256>>>(edge_index, edge_attr, E);

        int gb = (n_nodes * 32 + 255) / 256;
        gather_kernel<<<gb, 256>>>(out, n_nodes);
    } else {
        int no4 = out_size / 4;
        int zb = (no4 + 255) / 256; if (zb > 8192) zb = 8192;
        zero_out_kernel<<<zb, 256>>>((float4*)out, no4);
        int warps = (E + 31) / 32;
        int blocks = (warps * 32 + 255) / 256;
        scatter_f_kernel<<<blocks, 256>>>(edge_index, edge_attr, x, out, E);
    }
}

// round 12
// speedup vs baseline: 1.4803x; 1.4803x over previous
#include <cuda_runtime.h>
#include <cuda_fp16.h>
#include <cstdint>

// out[src] += edge_attr[e] * x[dst]   (E=1.6M, N=100k, D=32)
// Inputs: edge_index int32 [2,E], edge_attr f32 [E], x f32 [N,32]
// Output: f32 [N,32]
//
// R12: fp16 f16x2 RED accumulation into 4 parity-split buffers (halves the
// fp32 RMW sector wall), fp16 gather, fp32 combine. Buffers use a COMPACT
// runtime stride (n_nodes*16) so the prep zeroing exactly covers all of them
// (R11's capacity-stride layout left buffer tails un-zeroed across replays).

#define N_CAP  131072
#define NBUF   4

__device__ __half2 g_xh[N_CAP * 16];             // fp16 copy of x (row = 16 half2)
__device__ __half2 g_acc[NBUF * N_CAP * 16];     // flat; runtime stride n_nodes*16

__device__ __forceinline__ void red_add_h2(__half2* addr, __half2 v) {
    asm volatile("red.global.add.noftz.f16x2 [%0], %1;"
                 :: "l"(addr), "r"(*(unsigned int*)&v) : "memory");
}
__device__ __forceinline__ unsigned int ldcg_b32(const void* p) {
    unsigned int v;
    asm volatile("ld.global.cg.b32 %0, [%1];" : "=r"(v) : "l"(p));
    return v;
}
__device__ __forceinline__ void red_add_v4(float* addr, float4 v) {
    asm volatile("red.global.add.v4.f32 [%0], {%1, %2, %3, %4};"
                 :: "l"(addr), "f"(v.x), "f"(v.y), "f"(v.z), "f"(v.w)
                 : "memory");
}
__device__ __forceinline__ float4 ldcg_v4f(const float* p) {
    float4 v;
    asm volatile("ld.global.cg.v4.f32 {%0, %1, %2, %3}, [%4];"
                 : "=f"(v.x), "=f"(v.y), "=f"(v.z), "=f"(v.w)
                 : "l"(p));
    return v;
}

// ---- 1. prep: convert x -> fp16 AND zero the accumulation region ----------
// nacc4 = NBUF * n_nodes * 16 / 4 uint4 elems — exactly covers all 4 compact
// buffers, every replay.
__global__ void prep_kernel(const float* __restrict__ x, int nx4, int nacc4) {
    int i = blockIdx.x * blockDim.x + threadIdx.x;
    int stride = gridDim.x * blockDim.x;
    int nmax = nx4 > nacc4 ? nx4 : nacc4;
    uint4 z = make_uint4(0u, 0u, 0u, 0u);
    uint4* acc = (uint4*)g_acc;
    for (; i < nmax; i += stride) {
        if (i < nacc4) acc[i] = z;
        if (i < nx4) {
            float4 f = ((const float4*)x)[i];
            g_xh[i * 2]     = __floats2half2_rn(f.x, f.y);
            g_xh[i * 2 + 1] = __floats2half2_rn(f.z, f.w);
        }
    }
}

// ---- 2. scatter: fp16 gather + f16x2 RED into buffer ((e>>1)&3) -----------
#define EDGES_PER_WARP 32

__global__ __launch_bounds__(256) void scatter_h2_kernel(
        const int* __restrict__ edge_index,
        const float* __restrict__ edge_attr,
        int E, int buf_stride) {          // buf_stride = n_nodes * 16 (half2)
    int lane = threadIdx.x & 31;
    int slot = lane >> 4;              // 0..1 : which edge in the pair
    int h    = lane & 15;              // 0..15: which half2 of the row
    int warp = (blockIdx.x * blockDim.x + threadIdx.x) >> 5;
    int base = warp * EDGES_PER_WARP;
    if (base >= E) return;

    bool full = (base + EDGES_PER_WARP <= E);

    #pragma unroll 8
    for (int g = 0; g < EDGES_PER_WARP / 2; g++) {
        int e = base + g * 2 + slot;
        if (!full && e >= E) continue;

        int   src = __ldg(&edge_index[e]);
        int   dst = __ldg(&edge_index[E + e]);
        float a   = __ldg(&edge_attr[e]);

        unsigned int hb = ldcg_b32(&g_xh[(long)dst * 16 + h]);  // 1 half2 = 4B
        float2 f = __half22float2(*(__half2*)&hb);
        __half2 hv = __floats2half2_rn(a * f.x, a * f.y);

        // (e>>1)&3: both edges of one warp instruction use the SAME buffer
        int buf = (e >> 1) & 3;
        red_add_h2(&g_acc[(long)buf * buf_stride + (long)src * 16 + h], hv);
    }
}

// ---- 3. combine: out = fp32 sum of the 4 fp16 buffers ---------------------
__global__ void combine_kernel(float2* __restrict__ out, int n2, int buf_stride) {
    int i = blockIdx.x * blockDim.x + threadIdx.x;
    int stride = gridDim.x * blockDim.x;
    for (; i < n2; i += stride) {
        float2 s = make_float2(0.f, 0.f);
        #pragma unroll
        for (int b = 0; b < NBUF; b++) {
            float2 f = __half22float2(g_acc[(long)b * buf_stride + i]);
            s.x += f.x; s.y += f.y;
        }
        out[i] = s;
    }
}

// ---- fallback (R4-style fp32 direct scatter) for oversize inputs ----------
__global__ void zero_out_kernel(float4* __restrict__ out, int n4) {
    int i = blockIdx.x * blockDim.x + threadIdx.x;
    int stride = gridDim.x * blockDim.x;
    float4 z = make_float4(0.f, 0.f, 0.f, 0.f);
    for (; i < n4; i += stride) out[i] = z;
}
__global__ __launch_bounds__(256) void scatter_f_kernel(
        const int* __restrict__ edge_index,
        const float* __restrict__ edge_attr,
        const float* __restrict__ x,
        float* __restrict__ out, int E) {
    int lane = threadIdx.x & 31;
    int slot = lane >> 3;
    int fofs = (lane & 7) << 2;
    int warp = (blockIdx.x * blockDim.x + threadIdx.x) >> 5;
    int base = warp * 32;
    if (base >= E) return;
    for (int i = 0; i < 8; i++) {
        int e = base + i * 4 + slot;
        if (e < E) {
            int src = __ldg(&edge_index[e]);
            int dst = __ldg(&edge_index[E + e]);
            float a = __ldg(&edge_attr[e]);
            float4 v = ldcg_v4f(x + (long)dst * 32 + fofs);
            v.x *= a; v.y *= a; v.z *= a; v.w *= a;
            red_add_v4(out + (long)src * 32 + fofs, v);
        }
    }
}

extern "C" void kernel_launch(void* const* d_in, const int* in_sizes, int n_in,
                              void* d_out, int out_size) {
    const int*   edge_index = (const int*)d_in[0];
    const float* edge_attr  = (const float*)d_in[1];
    const float* x          = (const float*)d_in[2];
    float*       out        = (float*)d_out;

    int E       = in_sizes[0] / 2;
    int nx      = in_sizes[2];
    int n_nodes = nx / 32;

    if (n_nodes <= N_CAP && (nx & 3) == 0 && out_size == nx) {
        int buf_stride = n_nodes * 16;            // half2 per buffer
        int nx4   = nx / 4;                       // float4 elems of x
        int nacc4 = NBUF * buf_stride / 4;        // uint4 elems of accum

        int nmax = nx4 > nacc4 ? nx4 : nacc4;
        int pb = (nmax + 255) / 256; if (pb > 8192) pb = 8192;
        prep_kernel<<<pb, 256>>>(x, nx4, nacc4);

        int warps = (E + EDGES_PER_WARP - 1) / EDGES_PER_WARP;
        int blocks = (warps * 32 + 255) / 256;
        scatter_h2_kernel<<<blocks, 256>>>(edge_index, edge_attr, E, buf_stride);

        int n2 = n_nodes * 16;                    // float2 elems of out
        int cb = (n2 + 255) / 256; if (cb > 8192) cb = 8192;
        combine_kernel<<<cb, 256>>>((float2*)out, n2, buf_stride);
    } else {
        int no4 = out_size / 4;
        int zb = (no4 + 255) / 256; if (zb > 8192) zb = 8192;
        zero_out_kernel<<<zb, 256>>>((float4*)out, no4);
        int warps = (E + 31) / 32;
        int blocks = (warps * 32 + 255) / 256;
        scatter_f_kernel<<<blocks, 256>>>(edge_index, edge_attr, x, out, E);
    }
}